// round 11
// baseline (speedup 1.0000x reference)
#include <cuda_runtime.h>
#include <utility>
#include <cstddef>
#include <cstdint>

// Problem constants (fixed by the reference: N_COLS=16, ADD=3)
#define NC       16          // input columns
#define NTOT     696         // 16 + C(16,2)=120 + C(16,3)=560
#define NTOT4    174         // NTOT / 4
#define ROWS_PC  32          // rows per chunk (= lanes per warp)
#define NPART    6           // column parts (warps per block)
#define PF4      29          // float4s per part (29 * 6 = 174)
#define TPB      (32 * NPART)        // 192 threads
#define CHB      4           // chunks per block
#define BUFB     (ROWS_PC * NTOT * 4)   // 89,088 B per buffer (128B-multiple)
#define NBUF     2           // double buffer: 178,176 B dynamic smem

// ---------------------------------------------------------------------------
// Compile-time decode of output column g -> (i, j, k) subset indices.
// sel: 0 -> i, 1 -> j, 2 -> k.  Returns NC (=16) as "unused" sentinel.
__host__ __device__ constexpr int decode(int g, int sel) {
    if (g < NC) return sel == 0 ? g : NC;           // passthrough columns
    g -= NC;
    if (g < 120) {                                   // pairs, lexicographic
        int c = 0;
        for (int a = 0; a < NC; a++)
            for (int b = a + 1; b < NC; b++) {
                if (c == g) return sel == 0 ? a : (sel == 1 ? b : NC);
                c++;
            }
    } else {                                         // triples, lexicographic
        g -= 120;
        int c = 0;
        for (int a = 0; a < NC; a++)
            for (int b = a + 1; b < NC; b++)
                for (int d = b + 1; d < NC; d++) {
                    if (c == g) return sel == 0 ? a : (sel == 1 ? b : d);
                    c++;
                }
    }
    return NC;
}

// One output term; compile-time indices keep v[] in registers; association
// (v[i]*v[j])*v[k] lets ptxas CSE pair products across lexicographic runs.
// No register cap (R6 lesson: capping rematerializes serial FMUL chains).
template <int G>
__device__ __forceinline__ float term(const float (&v)[NC]) {
    constexpr int i = decode(G, 0);
    constexpr int j = decode(G, 1);
    constexpr int k = decode(G, 2);
    float r = v[i];
    if constexpr (j < NC) r = r * v[j];
    if constexpr (k < NC) r = r * v[k];
    return r;
}

__device__ __forceinline__ uint32_t smem_u32(const void* p) {
    uint32_t a;
    asm("{ .reg .u64 t; cvta.to.shared.u64 t, %1; cvt.u32.u64 %0, t; }" : "=r"(a) : "l"(p));
    return a;
}

// Warp W computes its row's float4 columns [PF4*W, PF4*W+PF4) into the LINEAR
// smem row image (no swizzle: the buffer must byte-match global layout for the
// 1D bulk copy). rowp = row base in the buffer.
template <int W, int... I>
__device__ __forceinline__ void compute_part(const float (&v)[NC], float4* rowp,
                                             std::integer_sequence<int, I...>) {
    ((rowp[PF4 * W + I] = make_float4(term<4 * (PF4 * W + I) + 0>(v),
                                      term<4 * (PF4 * W + I) + 1>(v),
                                      term<4 * (PF4 * W + I) + 2>(v),
                                      term<4 * (PF4 * W + I) + 3>(v))), ...);
}

__global__ void __launch_bounds__(TPB)
algebraic_bulk_kernel(const float* __restrict__ x, float* __restrict__ out) {
    extern __shared__ char sbuf[];            // NBUF x 89,088 B, 16B-aligned

    const int tid  = threadIdx.x;
    const int lane = tid & 31;                // row within chunk
    const int warp = tid >> 5;                // column part (warp-uniform)

    const int chunk0 = blockIdx.x * CHB;      // global chunk index base

    for (int c = 0; c < CHB; c++) {
        char* buf = sbuf + ((c & 1) * BUFB);

        // Reclaim buffer: allow NBUF-1 = 1 outstanding bulk group's smem read.
        if (c >= NBUF) {
            if (tid == 0)
                asm volatile("cp.async.bulk.wait_group.read 1;" ::: "memory");
        }
        __syncthreads();

        const size_t r0  = (size_t)(chunk0 + c) * ROWS_PC;   // chunk's first row
        const size_t row = r0 + lane;

        // Load this lane's input row (all 6 warps load the same 32 rows;
        // redundant reads hit L1/L2 — input is only 16 MB total).
        float v[NC];
        {
            const float4* xp = reinterpret_cast<const float4*>(x) + row * (NC / 4);
            float4 a = xp[0], b = xp[1], cc = xp[2], d = xp[3];
            v[0]  = a.x;  v[1]  = a.y;  v[2]  = a.z;  v[3]  = a.w;
            v[4]  = b.x;  v[5]  = b.y;  v[6]  = b.z;  v[7]  = b.w;
            v[8]  = cc.x; v[9]  = cc.y; v[10] = cc.z; v[11] = cc.w;
            v[12] = d.x;  v[13] = d.y;  v[14] = d.z;  v[15] = d.w;
        }

        float4* rowp = reinterpret_cast<float4*>(buf) + (size_t)lane * NTOT4;

        // Warp-uniform dispatch: each warp emits its 29 float4s (compile-time
        // column indices), zero intra-warp divergence.
        switch (warp) {
            case 0: compute_part<0>(v, rowp, std::make_integer_sequence<int, PF4>{}); break;
            case 1: compute_part<1>(v, rowp, std::make_integer_sequence<int, PF4>{}); break;
            case 2: compute_part<2>(v, rowp, std::make_integer_sequence<int, PF4>{}); break;
            case 3: compute_part<3>(v, rowp, std::make_integer_sequence<int, PF4>{}); break;
            case 4: compute_part<4>(v, rowp, std::make_integer_sequence<int, PF4>{}); break;
            case 5: compute_part<5>(v, rowp, std::make_integer_sequence<int, PF4>{}); break;
        }

        asm volatile("fence.proxy.async.shared::cta;" ::: "memory");
        __syncthreads();

        if (tid == 0) {
            // One fully-linear 89,088 B store: complete rows r0..r0+31,
            // contiguous and 128B-aligned in global memory.
            float* gdst = out + r0 * NTOT;
            uint32_t saddr = smem_u32(buf);
            asm volatile(
                "cp.async.bulk.global.shared::cta.bulk_group [%0], [%1], %2;"
                :: "l"(gdst), "r"(saddr), "r"((uint32_t)BUFB) : "memory");
            asm volatile("cp.async.bulk.commit_group;" ::: "memory");
        }
    }

    // Drain all bulk groups before the block retires (smem + global safety).
    if (tid == 0)
        asm volatile("cp.async.bulk.wait_group 0;" ::: "memory");
}

// ---------------------------------------------------------------------------
// Fallback (only if the smem-attribute opt-in fails): direct strided stores.
template <int... I>
__device__ __forceinline__ void store_all(const float (&v)[NC], float4* __restrict__ o,
                                          std::integer_sequence<int, I...>) {
    ((o[I] = make_float4(term<4 * I + 0>(v), term<4 * I + 1>(v),
                         term<4 * I + 2>(v), term<4 * I + 3>(v))), ...);
}

__global__ void __launch_bounds__(128)
algebraic_fallback_kernel(const float* __restrict__ x, float4* __restrict__ out4) {
    const size_t row = (size_t)blockIdx.x * 128 + threadIdx.x;
    float v[NC];
    const float4* xp = reinterpret_cast<const float4*>(x) + row * (NC / 4);
    float4 a = xp[0], b = xp[1], c = xp[2], d = xp[3];
    v[0]  = a.x; v[1]  = a.y; v[2]  = a.z; v[3]  = a.w;
    v[4]  = b.x; v[5]  = b.y; v[6]  = b.z; v[7]  = b.w;
    v[8]  = c.x; v[9]  = c.y; v[10] = c.z; v[11] = c.w;
    v[12] = d.x; v[13] = d.y; v[14] = d.z; v[15] = d.w;
    store_all(v, out4 + row * NTOT4, std::make_integer_sequence<int, NTOT4>{});
}

// ---------------------------------------------------------------------------
extern "C" void kernel_launch(void* const* d_in, const int* in_sizes, int n_in,
                              void* d_out, int out_size) {
    const float* x  = (const float*)d_in[0];
    const int nrows = in_sizes[0] / NC;                     // 262144
    const int nchunks = nrows / ROWS_PC;                    // 8192
    const int blocks  = nchunks / CHB;                      // 2048

    // Opt into 174 KB dynamic smem (host-side state change, not an allocation).
    static int attr_state = 0;   // 0 = untried, 1 = ok, -1 = failed
    if (attr_state == 0) {
        attr_state = (cudaFuncSetAttribute(algebraic_bulk_kernel,
                                           cudaFuncAttributeMaxDynamicSharedMemorySize,
                                           NBUF * BUFB) == cudaSuccess) ? 1 : -1;
    }

    if (attr_state == 1) {
        algebraic_bulk_kernel<<<blocks, TPB, NBUF * BUFB>>>(x, (float*)d_out);
    } else {
        algebraic_fallback_kernel<<<nrows / 128, 128>>>(x, (float4*)d_out);
    }
}

// round 13
// speedup vs baseline: 1.0474x; 1.0474x over previous
#include <cuda_runtime.h>
#include <cuda.h>          // CUtensorMap type (header-only use; symbol via runtime lookup)
#include <utility>
#include <cstddef>
#include <cstdint>

// Problem constants (fixed by the reference: N_COLS=16, ADD=3)
#define NC      16         // input columns
#define NTOT    696        // 16 + C(16,2)=120 + C(16,3)=560
#define NTOT4   174        // NTOT / 4
#define TPB     128        // threads per block == rows per tile
#define CCOLS   32         // output columns per full TMA chunk (21*32 + 24 = 696)
#define NFULL   21         // full 32-col chunks
#define LASTC   24         // final chunk columns
#define SPAN    128        // SW128 swizzle span = smem row pitch (bytes)
#define BUFB    (TPB * SPAN)   // 16 KB per buffer
#define NBUF    6          // 6-deep ring: 96 KB dynamic smem (opt-in attribute)
#define GRID    296        // 148 SMs x 2 resident blocks: persistent single wave
#define NTILES  2048       // 262144 rows / 128

// ---------------------------------------------------------------------------
// Compile-time decode of output column g -> (i, j, k) subset indices.
// sel: 0 -> i, 1 -> j, 2 -> k.  Returns NC (=16) as "unused" sentinel.
__host__ __device__ constexpr int decode(int g, int sel) {
    if (g < NC) return sel == 0 ? g : NC;           // passthrough columns
    g -= NC;
    if (g < 120) {                                   // pairs, lexicographic
        int c = 0;
        for (int a = 0; a < NC; a++)
            for (int b = a + 1; b < NC; b++) {
                if (c == g) return sel == 0 ? a : (sel == 1 ? b : NC);
                c++;
            }
    } else {                                         // triples, lexicographic
        g -= 120;
        int c = 0;
        for (int a = 0; a < NC; a++)
            for (int b = a + 1; b < NC; b++)
                for (int d = b + 1; d < NC; d++) {
                    if (c == g) return sel == 0 ? a : (sel == 1 ? b : d);
                    c++;
                }
    }
    return NC;
}

// One output term; compile-time indices keep v[] in registers. NO register
// cap: ptxas caching pair products across chunks keeps the per-chunk compute
// phase short (R6 lesson: capping regs rematerializes serial FMUL chains and
// the barrier-paced chunk round stretches 2-3x).
template <int G>
__device__ __forceinline__ float term(const float (&v)[NC]) {
    constexpr int i = decode(G, 0);
    constexpr int j = decode(G, 1);
    constexpr int k = decode(G, 2);
    float r = v[i];
    if constexpr (j < NC) r = r * v[j];
    if constexpr (k < NC) r = r * v[k];
    return r;
}

__device__ __forceinline__ uint32_t smem_u32(const void* p) {
    uint32_t a;
    asm("{ .reg .u64 t; cvta.to.shared.u64 t, %1; cvt.u32.u64 %0, t; }" : "=r"(a) : "l"(p));
    return a;
}

// Thread tid writes its row's float4s for the chunk starting at column C0
// into the SW128-swizzled tile: row pitch 128 B, logical atom I lands at
// physical atom I^(tid&7) -> conflict-free STS.128 (per-I, atoms distinct
// across the 8-lane subphase).
template <int C0, int... I>
__device__ __forceinline__ void compute_chunk(const float (&v)[NC], char* buf, int tid,
                                              std::integer_sequence<int, I...>) {
    ((*reinterpret_cast<float4*>(buf + tid * SPAN + ((I ^ (tid & 7)) << 4)) =
          make_float4(term<C0 + 4 * I + 0>(v),
                      term<C0 + 4 * I + 1>(v),
                      term<C0 + 4 * I + 2>(v),
                      term<C0 + 4 * I + 3>(v))), ...);
}

// One pipelined chunk. The buffer ring rotates continuously across tiles via
// the runtime 'slot'; the unconditional wait_group.read 5 is a no-op until
// 6 groups are in flight, then guarantees the slot being reused has been read.
template <int C, int NF4>
__device__ __forceinline__ void do_chunk(const float (&v)[NC], char* sbase, int tid,
                                         const CUtensorMap* pmap, int row0, int& slot) {
    char* buf = sbase + slot * BUFB;
    if (tid == 0)
        asm volatile("cp.async.bulk.wait_group.read 5;" ::: "memory");
    __syncthreads();
    compute_chunk<C * CCOLS>(v, buf, tid, std::make_integer_sequence<int, NF4>{});
    asm volatile("fence.proxy.async.shared::cta;" ::: "memory");
    __syncthreads();
    if (tid == 0) {
        uint32_t saddr = smem_u32(buf);
        asm volatile(
            "cp.async.bulk.tensor.2d.global.shared::cta.tile.bulk_group [%0, {%1, %2}], [%3];"
            :: "l"(pmap), "r"(C * CCOLS), "r"(row0), "r"(saddr) : "memory");
        asm volatile("cp.async.bulk.commit_group;" ::: "memory");
    }
    slot = (slot + 1 < NBUF) ? slot + 1 : 0;
}

template <int... Cs>
__device__ __forceinline__ void do_full_chunks(const float (&v)[NC], char* sbase, int tid,
                                               const CUtensorMap* pmap, int row0, int& slot,
                                               std::integer_sequence<int, Cs...>) {
    (do_chunk<Cs, CCOLS / 4>(v, sbase, tid, pmap, row0, slot), ...);
}

__global__ void __launch_bounds__(TPB)
algebraic_tma_kernel(const float* __restrict__ x,
                     const __grid_constant__ CUtensorMap tmap_a,   // box [32,128]
                     const __grid_constant__ CUtensorMap tmap_b) { // box [24,128]
    extern __shared__ char sbuf[];            // 6 x 16 KB ring

    const int tid = threadIdx.x;
    int slot = 0;                             // ring slot, persists across tiles

    // Persistent: this block strides over tiles; the TMA ring never drains
    // between tiles (only once, at block end).
    for (int tile = blockIdx.x; tile < NTILES; tile += GRID) {
        const int row0 = tile * TPB;

        float v[NC];
        {
            const float4* xp = reinterpret_cast<const float4*>(x) +
                               ((size_t)row0 + tid) * (NC / 4);
            float4 a = xp[0], b = xp[1], c = xp[2], d = xp[3];
            v[0]  = a.x; v[1]  = a.y; v[2]  = a.z; v[3]  = a.w;
            v[4]  = b.x; v[5]  = b.y; v[6]  = b.z; v[7]  = b.w;
            v[8]  = c.x; v[9]  = c.y; v[10] = c.z; v[11] = c.w;
            v[12] = d.x; v[13] = d.y; v[14] = d.z; v[15] = d.w;
        }

        // 21 full 32-col chunks through tmap_a, final 24-col chunk via tmap_b.
        do_full_chunks(v, sbuf, tid, &tmap_a, row0, slot,
                       std::make_integer_sequence<int, NFULL>{});
        do_chunk<NFULL, LASTC / 4>(v, sbuf, tid, &tmap_b, row0, slot);
    }

    if (tid == 0)
        asm volatile("cp.async.bulk.wait_group 0;" ::: "memory");
}

// ---------------------------------------------------------------------------
// Fallback (only if tensormap creation / smem opt-in fails): direct stores.
template <int... I>
__device__ __forceinline__ void store_all(const float (&v)[NC], float4* __restrict__ o,
                                          std::integer_sequence<int, I...>) {
    ((o[I] = make_float4(term<4 * I + 0>(v), term<4 * I + 1>(v),
                         term<4 * I + 2>(v), term<4 * I + 3>(v))), ...);
}

__global__ void __launch_bounds__(TPB)
algebraic_fallback_kernel(const float* __restrict__ x, float4* __restrict__ out4) {
    const size_t row = (size_t)blockIdx.x * TPB + threadIdx.x;
    float v[NC];
    const float4* xp = reinterpret_cast<const float4*>(x) + row * (NC / 4);
    float4 a = xp[0], b = xp[1], c = xp[2], d = xp[3];
    v[0]  = a.x; v[1]  = a.y; v[2]  = a.z; v[3]  = a.w;
    v[4]  = b.x; v[5]  = b.y; v[6]  = b.z; v[7]  = b.w;
    v[8]  = c.x; v[9]  = c.y; v[10] = c.z; v[11] = c.w;
    v[12] = d.x; v[13] = d.y; v[14] = d.z; v[15] = d.w;
    store_all(v, out4 + row * NTOT4, std::make_integer_sequence<int, NTOT4>{});
}

// ---------------------------------------------------------------------------
extern "C" void kernel_launch(void* const* d_in, const int* in_sizes, int n_in,
                              void* d_out, int out_size) {
    const float* x  = (const float*)d_in[0];
    const int nrows = in_sizes[0] / NC;            // 262144 (multiple of 128)

    // Resolve cuTensorMapEncodeTiled through the runtime (no -lcuda link dep).
    typedef CUresult (*EncodeFn)(CUtensorMap*, CUtensorMapDataType, cuuint32_t, void*,
                                 const cuuint64_t*, const cuuint64_t*, const cuuint32_t*,
                                 const cuuint32_t*, CUtensorMapInterleave, CUtensorMapSwizzle,
                                 CUtensorMapL2promotion, CUtensorMapFloatOOBfill);
    EncodeFn encode = nullptr;
    {
        void* p = nullptr;
        cudaDriverEntryPointQueryResult st;
        if (cudaGetDriverEntryPointByVersion("cuTensorMapEncodeTiled", &p, 12000,
                                             cudaEnableDefault, &st) == cudaSuccess &&
            st == cudaDriverEntryPointSuccess)
            encode = (EncodeFn)p;
    }

    alignas(64) CUtensorMap tmap_a, tmap_b;
    bool tma_ok = false;
    if (encode) {
        cuuint64_t dims[2]    = {(cuuint64_t)NTOT, (cuuint64_t)nrows};
        cuuint64_t strides[1] = {(cuuint64_t)NTOT * sizeof(float)};   // 2784 B, 16B-multiple
        cuuint32_t estr[2]    = {1, 1};
        cuuint32_t box_a[2]   = {CCOLS, TPB};                         // 128 B x 128 rows
        cuuint32_t box_b[2]   = {LASTC, TPB};                         //  96 B x 128 rows
        bool oka = (encode(&tmap_a, CU_TENSOR_MAP_DATA_TYPE_FLOAT32, 2, d_out,
                           dims, strides, box_a, estr,
                           CU_TENSOR_MAP_INTERLEAVE_NONE, CU_TENSOR_MAP_SWIZZLE_128B,
                           CU_TENSOR_MAP_L2_PROMOTION_L2_128B,
                           CU_TENSOR_MAP_FLOAT_OOB_FILL_NONE) == CUDA_SUCCESS);
        bool okb = (encode(&tmap_b, CU_TENSOR_MAP_DATA_TYPE_FLOAT32, 2, d_out,
                           dims, strides, box_b, estr,
                           CU_TENSOR_MAP_INTERLEAVE_NONE, CU_TENSOR_MAP_SWIZZLE_128B,
                           CU_TENSOR_MAP_L2_PROMOTION_L2_128B,
                           CU_TENSOR_MAP_FLOAT_OOB_FILL_NONE) == CUDA_SUCCESS);
        tma_ok = oka && okb;
    }

    if (tma_ok) {
        // Opt into 96 KB dynamic smem (host state change, not an allocation).
        static int attr_state = 0;   // 0 = untried, 1 = ok, -1 = failed
        if (attr_state == 0) {
            attr_state = (cudaFuncSetAttribute(algebraic_tma_kernel,
                                               cudaFuncAttributeMaxDynamicSharedMemorySize,
                                               NBUF * BUFB) == cudaSuccess) ? 1 : -1;
        }
        if (attr_state == 1) {
            algebraic_tma_kernel<<<GRID, TPB, NBUF * BUFB>>>(x, tmap_a, tmap_b);
            return;
        }
    }
    algebraic_fallback_kernel<<<nrows / TPB, TPB>>>(x, (float4*)d_out);
}

// round 15
// speedup vs baseline: 1.1547x; 1.1024x over previous
#include <cuda_runtime.h>
#include <cuda.h>          // CUtensorMap type (header-only use; symbol via runtime lookup)
#include <utility>
#include <cstddef>
#include <cstdint>

// Problem constants (fixed by the reference: N_COLS=16, ADD=3)
#define NC      16         // input columns
#define NTOT    696        // 16 + C(16,2)=120 + C(16,3)=560
#define NTOT4   174        // NTOT / 4
#define TPB     128        // threads per block; 4 warps, each owns 32 rows
#define WROWS   32         // rows per warp tile (= lanes)
#define CCOLS   32         // output columns per full TMA chunk (21*32 + 24 = 696)
#define NFULL   21         // full 32-col chunks
#define LASTC   24         // final chunk columns
#define SPAN    128        // SW128 swizzle span = smem row pitch (bytes)
#define WBUF    (WROWS * SPAN)     // 4 KB per warp buffer
#define NBUF    4                  // per-warp ring depth
#define WRING   (NBUF * WBUF)      // 16 KB per warp
#define SMEMB   (4 * WRING)        // 64 KB per block (opt-in attribute)

// ---------------------------------------------------------------------------
// Compile-time decode of output column g -> (i, j, k) subset indices.
// sel: 0 -> i, 1 -> j, 2 -> k.  Returns NC (=16) as "unused" sentinel.
__host__ __device__ constexpr int decode(int g, int sel) {
    if (g < NC) return sel == 0 ? g : NC;           // passthrough columns
    g -= NC;
    if (g < 120) {                                   // pairs, lexicographic
        int c = 0;
        for (int a = 0; a < NC; a++)
            for (int b = a + 1; b < NC; b++) {
                if (c == g) return sel == 0 ? a : (sel == 1 ? b : NC);
                c++;
            }
    } else {                                         // triples, lexicographic
        g -= 120;
        int c = 0;
        for (int a = 0; a < NC; a++)
            for (int b = a + 1; b < NC; b++)
                for (int d = b + 1; d < NC; d++) {
                    if (c == g) return sel == 0 ? a : (sel == 1 ? b : d);
                    c++;
                }
    }
    return NC;
}

// One output term; compile-time indices keep v[] in registers. NO register
// cap (R6 lesson): ptxas caching pair products across chunks keeps the
// per-chunk compute phase short.
template <int G>
__device__ __forceinline__ float term(const float (&v)[NC]) {
    constexpr int i = decode(G, 0);
    constexpr int j = decode(G, 1);
    constexpr int k = decode(G, 2);
    float r = v[i];
    if constexpr (j < NC) r = r * v[j];
    if constexpr (k < NC) r = r * v[k];
    return r;
}

__device__ __forceinline__ uint32_t smem_u32(const void* p) {
    uint32_t a;
    asm("{ .reg .u64 t; cvta.to.shared.u64 t, %1; cvt.u32.u64 %0, t; }" : "=r"(a) : "l"(p));
    return a;
}

// Lane writes its row's float4s for the chunk starting at column C0 into the
// warp-private SW128-swizzled 32-row tile: row pitch 128 B, logical atom I at
// physical atom I^(lane&7) -> conflict-free STS.128.
template <int C0, int... I>
__device__ __forceinline__ void compute_chunk(const float (&v)[NC], char* buf, int lane,
                                              std::integer_sequence<int, I...>) {
    ((*reinterpret_cast<float4*>(buf + lane * SPAN + ((I ^ (lane & 7)) << 4)) =
          make_float4(term<C0 + 4 * I + 0>(v),
                      term<C0 + 4 * I + 1>(v),
                      term<C0 + 4 * I + 2>(v),
                      term<C0 + 4 * I + 3>(v))), ...);
}

// One warp-private pipelined chunk: reclaim ring slot (lane 0 tracks the
// warp's bulk groups) -> compute -> fence (all lanes) -> lane 0 TMA + commit.
// No block barriers anywhere: each warp is an independent TMA pipeline.
template <int C, int NF4>
__device__ __forceinline__ void do_chunk(const float (&v)[NC], char* wbase, int lane,
                                         const CUtensorMap* pmap, int wrow0) {
    char* buf = wbase + (C % NBUF) * WBUF;
    if constexpr (C >= NBUF) {
        if (lane == 0)
            asm volatile("cp.async.bulk.wait_group.read 3;" ::: "memory");
    }
    __syncwarp();
    compute_chunk<C * CCOLS>(v, buf, lane, std::make_integer_sequence<int, NF4>{});
    asm volatile("fence.proxy.async.shared::cta;" ::: "memory");
    __syncwarp();
    if (lane == 0) {
        uint32_t saddr = smem_u32(buf);
        asm volatile(
            "cp.async.bulk.tensor.2d.global.shared::cta.tile.bulk_group [%0, {%1, %2}], [%3];"
            :: "l"(pmap), "r"(C * CCOLS), "r"(wrow0), "r"(saddr) : "memory");
        asm volatile("cp.async.bulk.commit_group;" ::: "memory");
    }
}

template <int... Cs>
__device__ __forceinline__ void do_full_chunks(const float (&v)[NC], char* wbase, int lane,
                                               const CUtensorMap* pmap, int wrow0,
                                               std::integer_sequence<int, Cs...>) {
    (do_chunk<Cs, CCOLS / 4>(v, wbase, lane, pmap, wrow0), ...);
}

__global__ void __launch_bounds__(TPB)
algebraic_tma_kernel(const float* __restrict__ x,
                     const __grid_constant__ CUtensorMap tmap_a,   // box [32,32]
                     const __grid_constant__ CUtensorMap tmap_b) { // box [24,32]
    extern __shared__ char sbuf[];            // 4 warps x (4 x 4 KB) rings

    const int tid   = threadIdx.x;
    const int lane  = tid & 31;
    const int warp  = tid >> 5;
    const int wrow0 = blockIdx.x * TPB + warp * WROWS;   // warp's first row

    float v[NC];
    {
        const float4* xp = reinterpret_cast<const float4*>(x) +
                           ((size_t)wrow0 + lane) * (NC / 4);
        float4 a = xp[0], b = xp[1], c = xp[2], d = xp[3];
        v[0]  = a.x; v[1]  = a.y; v[2]  = a.z; v[3]  = a.w;
        v[4]  = b.x; v[5]  = b.y; v[6]  = b.z; v[7]  = b.w;
        v[8]  = c.x; v[9]  = c.y; v[10] = c.z; v[11] = c.w;
        v[12] = d.x; v[13] = d.y; v[14] = d.z; v[15] = d.w;
    }

    char* wbase = sbuf + warp * WRING;

    // 21 full 32-col chunks through tmap_a, final 24-col chunk via tmap_b.
    do_full_chunks(v, wbase, lane, &tmap_a, wrow0,
                   std::make_integer_sequence<int, NFULL>{});
    do_chunk<NFULL, LASTC / 4>(v, wbase, lane, &tmap_b, wrow0);

    // Drain this warp's groups before the block retires (smem reuse safety).
    if (lane == 0)
        asm volatile("cp.async.bulk.wait_group 0;" ::: "memory");
}

// ---------------------------------------------------------------------------
// Fallback (only if tensormap creation / smem opt-in fails): direct stores.
template <int... I>
__device__ __forceinline__ void store_all(const float (&v)[NC], float4* __restrict__ o,
                                          std::integer_sequence<int, I...>) {
    ((o[I] = make_float4(term<4 * I + 0>(v), term<4 * I + 1>(v),
                         term<4 * I + 2>(v), term<4 * I + 3>(v))), ...);
}

__global__ void __launch_bounds__(TPB)
algebraic_fallback_kernel(const float* __restrict__ x, float4* __restrict__ out4) {
    const size_t row = (size_t)blockIdx.x * TPB + threadIdx.x;
    float v[NC];
    const float4* xp = reinterpret_cast<const float4*>(x) + row * (NC / 4);
    float4 a = xp[0], b = xp[1], c = xp[2], d = xp[3];
    v[0]  = a.x; v[1]  = a.y; v[2]  = a.z; v[3]  = a.w;
    v[4]  = b.x; v[5]  = b.y; v[6]  = b.z; v[7]  = b.w;
    v[8]  = c.x; v[9]  = c.y; v[10] = c.z; v[11] = c.w;
    v[12] = d.x; v[13] = d.y; v[14] = d.z; v[15] = d.w;
    store_all(v, out4 + row * NTOT4, std::make_integer_sequence<int, NTOT4>{});
}

// ---------------------------------------------------------------------------
extern "C" void kernel_launch(void* const* d_in, const int* in_sizes, int n_in,
                              void* d_out, int out_size) {
    const float* x  = (const float*)d_in[0];
    const int nrows = in_sizes[0] / NC;            // 262144 (multiple of 128)
    const int blocks = nrows / TPB;                // 2048

    // Resolve cuTensorMapEncodeTiled through the runtime (no -lcuda link dep).
    typedef CUresult (*EncodeFn)(CUtensorMap*, CUtensorMapDataType, cuuint32_t, void*,
                                 const cuuint64_t*, const cuuint64_t*, const cuuint32_t*,
                                 const cuuint32_t*, CUtensorMapInterleave, CUtensorMapSwizzle,
                                 CUtensorMapL2promotion, CUtensorMapFloatOOBfill);
    EncodeFn encode = nullptr;
    {
        void* p = nullptr;
        cudaDriverEntryPointQueryResult st;
        if (cudaGetDriverEntryPointByVersion("cuTensorMapEncodeTiled", &p, 12000,
                                             cudaEnableDefault, &st) == cudaSuccess &&
            st == cudaDriverEntryPointSuccess)
            encode = (EncodeFn)p;
    }

    alignas(64) CUtensorMap tmap_a, tmap_b;
    bool tma_ok = false;
    if (encode) {
        cuuint64_t dims[2]    = {(cuuint64_t)NTOT, (cuuint64_t)nrows};
        cuuint64_t strides[1] = {(cuuint64_t)NTOT * sizeof(float)};   // 2784 B, 16B-multiple
        cuuint32_t estr[2]    = {1, 1};
        cuuint32_t box_a[2]   = {CCOLS, WROWS};                       // 128 B x 32 rows
        cuuint32_t box_b[2]   = {LASTC, WROWS};                       //  96 B x 32 rows
        bool oka = (encode(&tmap_a, CU_TENSOR_MAP_DATA_TYPE_FLOAT32, 2, d_out,
                           dims, strides, box_a, estr,
                           CU_TENSOR_MAP_INTERLEAVE_NONE, CU_TENSOR_MAP_SWIZZLE_128B,
                           CU_TENSOR_MAP_L2_PROMOTION_L2_128B,
                           CU_TENSOR_MAP_FLOAT_OOB_FILL_NONE) == CUDA_SUCCESS);
        bool okb = (encode(&tmap_b, CU_TENSOR_MAP_DATA_TYPE_FLOAT32, 2, d_out,
                           dims, strides, box_b, estr,
                           CU_TENSOR_MAP_INTERLEAVE_NONE, CU_TENSOR_MAP_SWIZZLE_128B,
                           CU_TENSOR_MAP_L2_PROMOTION_L2_128B,
                           CU_TENSOR_MAP_FLOAT_OOB_FILL_NONE) == CUDA_SUCCESS);
        tma_ok = oka && okb;
    }

    if (tma_ok) {
        // Opt into 64 KB dynamic smem (host state change, not an allocation).
        static int attr_state = 0;   // 0 = untried, 1 = ok, -1 = failed
        if (attr_state == 0) {
            attr_state = (cudaFuncSetAttribute(algebraic_tma_kernel,
                                               cudaFuncAttributeMaxDynamicSharedMemorySize,
                                               SMEMB) == cudaSuccess) ? 1 : -1;
        }
        if (attr_state == 1) {
            algebraic_tma_kernel<<<blocks, TPB, SMEMB>>>(x, tmap_a, tmap_b);
            return;
        }
    }
    algebraic_fallback_kernel<<<blocks, TPB>>>(x, (float4*)d_out);
}